// round 1
// baseline (speedup 1.0000x reference)
#include <cuda_runtime.h>

// Problem constants (fixed by the reference)
#define BB 8
#define NN 8192
#define MM 2048
#define NUM_ITER 4
#define BASE_ALPHA 0.1f

// Scratch: nearest point (xyz) + min_dist per (b,n); per-iter per-batch max bits.
__device__ float4 g_near[BB * NN];
__device__ int    g_maxbits[NUM_ITER * BB];

// ---------------------------------------------------------------------------
// Init: copy pred -> out (refined works in-place in d_out), zero max slots.
// ---------------------------------------------------------------------------
__global__ void ipgr_init_kernel(const float* __restrict__ pred,
                                 float* __restrict__ out) {
    int i = blockIdx.x * blockDim.x + threadIdx.x;
    if (i < NUM_ITER * BB) g_maxbits[i] = 0;
    const int total = BB * NN * 3;
    for (; i < total; i += gridDim.x * blockDim.x) out[i] = pred[i];
}

// ---------------------------------------------------------------------------
// Phase A: for each pred point, find nearest partial point (squared-distance
// argmin, first-index tie-break), store nearest xyz + sqrt(min d2), and
// atomically accumulate per-batch max of min_dist.
// grid = (NN/256, BB), block = 256
// ---------------------------------------------------------------------------
__global__ void ipgr_nn_kernel(const float* __restrict__ refined,
                               const float* __restrict__ partial,
                               int iter) {
    __shared__ float4 sy[MM];  // {y.x, y.y, y.z, |y|^2}  -> 32 KB

    const int b = blockIdx.y;
    const float* p = partial + (size_t)b * MM * 3;

    for (int j = threadIdx.x; j < MM; j += blockDim.x) {
        float yx = p[j * 3 + 0];
        float yy = p[j * 3 + 1];
        float yz = p[j * 3 + 2];
        sy[j] = make_float4(yx, yy, yz, yx * yx + yy * yy + yz * yz);
    }
    __syncthreads();

    const int n  = blockIdx.x * blockDim.x + threadIdx.x;
    const int gi = b * NN + n;

    const float x0 = refined[gi * 3 + 0];
    const float x1 = refined[gi * 3 + 1];
    const float x2 = refined[gi * 3 + 2];
    const float xs = x0 * x0 + x1 * x1 + x2 * x2;

    float best = 3.4e38f;
    int   bidx = 0;

#pragma unroll 8
    for (int m = 0; m < MM; m++) {
        float4 y = sy[m];
        float s  = xs + y.w;
        float xy = x0 * y.x;
        xy = fmaf(x1, y.y, xy);
        xy = fmaf(x2, y.z, xy);
        float d2 = fmaf(-2.0f, xy, s);  // x2 + y2 - 2*x.y (same formula as ref)
        if (d2 < best) { best = d2; bidx = m; }
    }

    float md = sqrtf(fmaxf(best, 0.0f));
    float4 nr = sy[bidx];
    g_near[gi] = make_float4(nr.x, nr.y, nr.z, md);

    // warp max reduce, one atomic per warp (md >= 0 so int ordering == float)
    float w = md;
#pragma unroll
    for (int o = 16; o > 0; o >>= 1)
        w = fmaxf(w, __shfl_xor_sync(0xffffffffu, w, o));
    if ((threadIdx.x & 31) == 0)
        atomicMax(&g_maxbits[iter * BB + b], __float_as_int(w));
}

// ---------------------------------------------------------------------------
// Phase B: blend refined toward nearest with distance-normalized alpha.
// grid = BB*NN/256, block = 256
// ---------------------------------------------------------------------------
__global__ void ipgr_update_kernel(float* __restrict__ refined, int iter) {
    const int gi = blockIdx.x * blockDim.x + threadIdx.x;  // b*NN + n
    const int b  = gi / NN;

    float4 nd = g_near[gi];
    float  mx = __int_as_float(g_maxbits[iter * BB + b]);
    float  dn = nd.w / (mx + 1e-6f);
    float  alpha = BASE_ALPHA * (2.0f - dn);

    float r0 = refined[gi * 3 + 0];
    float r1 = refined[gi * 3 + 1];
    float r2 = refined[gi * 3 + 2];
    refined[gi * 3 + 0] = fmaf(alpha, nd.x - r0, r0);
    refined[gi * 3 + 1] = fmaf(alpha, nd.y - r1, r1);
    refined[gi * 3 + 2] = fmaf(alpha, nd.z - r2, r2);
}

// ---------------------------------------------------------------------------
extern "C" void kernel_launch(void* const* d_in, const int* in_sizes, int n_in,
                              void* d_out, int out_size) {
    const float* pred    = (const float*)d_in[0];  // [8, 8192, 3] f32
    const float* partial = (const float*)d_in[1];  // [8, 2048, 3] f32
    float* out = (float*)d_out;                     // [8, 8192, 3] f32

    (void)in_sizes; (void)n_in; (void)out_size;

    ipgr_init_kernel<<<256, 256>>>(pred, out);

    dim3 gridA(NN / 256, BB);
    for (int it = 0; it < NUM_ITER; it++) {
        ipgr_nn_kernel<<<gridA, 256>>>(out, partial, it);
        ipgr_update_kernel<<<(BB * NN) / 256, 256>>>(out, it);
    }
}

// round 2
// speedup vs baseline: 1.2794x; 1.2794x over previous
#include <cuda_runtime.h>
#include <cstdint>

#define BB 8
#define NN 8192
#define MM 2048
#define NUM_ITER 4
#define BASE_ALPHA 0.1f

// Scratch: nearest point (xyz) + min_dist per (b,n); per-iter per-batch max bits.
__device__ float4 g_near[BB * NN];
__device__ int    g_maxbits[NUM_ITER * BB];

// ---------------------------------------------------------------------------
// f32x2 packed helpers (Blackwell-only FFMA2 path, PTX fma.rn.f32x2)
// ---------------------------------------------------------------------------
__device__ __forceinline__ uint64_t pack2(float lo, float hi) {
    uint64_t r;
    asm("mov.b64 %0, {%1, %2};" : "=l"(r) : "f"(lo), "f"(hi));
    return r;
}
__device__ __forceinline__ uint64_t ffma2(uint64_t a, uint64_t b, uint64_t c) {
    uint64_t d;
    asm("fma.rn.f32x2 %0, %1, %2, %3;" : "=l"(d) : "l"(a), "l"(b), "l"(c));
    return d;
}
__device__ __forceinline__ void unpack2(uint64_t v, float& lo, float& hi) {
    asm("mov.b64 {%0, %1}, %2;" : "=f"(lo), "=f"(hi) : "l"(v));
}

// ---------------------------------------------------------------------------
// Init: copy pred -> out (refined lives in d_out), zero max slots.
// ---------------------------------------------------------------------------
__global__ void ipgr_init_kernel(const float4* __restrict__ pred,
                                 float4* __restrict__ out) {
    int i = blockIdx.x * blockDim.x + threadIdx.x;
    if (i < NUM_ITER * BB) g_maxbits[i] = 0;
    const int total4 = BB * NN * 3 / 4;  // 49152 float4
    for (; i < total4; i += gridDim.x * blockDim.x) out[i] = pred[i];
}

// ---------------------------------------------------------------------------
// Phase A: nearest-neighbor search.
// block = 128 threads, grid = (NN/128, BB) = (64, 8).
// Lane layout: q = lane>>3 (M-quarter), sub = lane&7.
// Each thread processes 4 consecutive pred points over 512 m's (its quarter).
// The 4 quarters of each point live in lanes {sub, sub+8, sub+16, sub+24} of
// one warp and are merged with two shfl-xor rounds (tie -> smaller m).
// Inner comparison key: t = |y|^2/2 - x.y  (argmin-equivalent to d2 since
// |x|^2 is constant per point); d2 = xs + 2*t recovered at the end.
// ---------------------------------------------------------------------------
__global__ void __launch_bounds__(128, 4)
ipgr_nn_kernel(const float* __restrict__ refined,
               const float* __restrict__ partial,
               int iter) {
    // SoA tile of partial: yx | yy | yz | yh(=0.5*|y|^2), each MM floats.
    __shared__ __align__(16) float sm[4 * MM];

    const int b = blockIdx.y;
    const float* p = partial + (size_t)b * MM * 3;

    for (int m = threadIdx.x; m < MM; m += 128) {
        float yx = p[m * 3 + 0];
        float yy = p[m * 3 + 1];
        float yz = p[m * 3 + 2];
        sm[m]          = yx;
        sm[MM + m]     = yy;
        sm[2 * MM + m] = yz;
        sm[3 * MM + m] = 0.5f * fmaf(yz, yz, fmaf(yy, yy, yx * yx));
    }
    __syncthreads();

    const int lane = threadIdx.x & 31;
    const int warp = threadIdx.x >> 5;
    const int q    = lane >> 3;        // which M-quarter this lane scans
    const int sub  = lane & 7;
    const int n0   = blockIdx.x * 128 + warp * 32 + sub * 4;  // 4 points/thread

    // Load 4 pred points; pack negated coords for FFMA2 (t = yh - x.y).
    uint64_t xp0[4], xp1[4], xp2[4];
    float xs[4];
    {
        const float* rp = refined + ((size_t)b * NN + n0) * 3;
#pragma unroll
        for (int i = 0; i < 4; i++) {
            float x0 = rp[i * 3 + 0];
            float x1 = rp[i * 3 + 1];
            float x2 = rp[i * 3 + 2];
            xp0[i] = pack2(-x0, -x0);
            xp1[i] = pack2(-x1, -x1);
            xp2[i] = pack2(-x2, -x2);
            xs[i]  = fmaf(x2, x2, fmaf(x1, x1, x0 * x0));
        }
    }

    float best[4] = {3.4e38f, 3.4e38f, 3.4e38f, 3.4e38f};
    int   bidx[4] = {0, 0, 0, 0};

    // Each ulonglong2 = 4 consecutive m's of one SoA component.
    const ulonglong2* pyx = reinterpret_cast<const ulonglong2*>(sm)           + q * 128;
    const ulonglong2* pyy = reinterpret_cast<const ulonglong2*>(sm + MM)      + q * 128;
    const ulonglong2* pyz = reinterpret_cast<const ulonglong2*>(sm + 2 * MM)  + q * 128;
    const ulonglong2* pyh = reinterpret_cast<const ulonglong2*>(sm + 3 * MM)  + q * 128;
    const int mbase = q * 512;

#pragma unroll 4
    for (int k = 0; k < 128; k++) {
        ulonglong2 vx = pyx[k];
        ulonglong2 vy = pyy[k];
        ulonglong2 vz = pyz[k];
        ulonglong2 vh = pyh[k];
        const int m = mbase + k * 4;
#pragma unroll
        for (int i = 0; i < 4; i++) {
            uint64_t t01 = ffma2(xp0[i], vx.x, vh.x);
            t01 = ffma2(xp1[i], vy.x, t01);
            t01 = ffma2(xp2[i], vz.x, t01);
            uint64_t t23 = ffma2(xp0[i], vx.y, vh.y);
            t23 = ffma2(xp1[i], vy.y, t23);
            t23 = ffma2(xp2[i], vz.y, t23);
            float t0, t1, t2, t3;
            unpack2(t01, t0, t1);
            unpack2(t23, t2, t3);
            if (t0 < best[i]) { best[i] = t0; bidx[i] = m; }
            if (t1 < best[i]) { best[i] = t1; bidx[i] = m + 1; }
            if (t2 < best[i]) { best[i] = t2; bidx[i] = m + 2; }
            if (t3 < best[i]) { best[i] = t3; bidx[i] = m + 3; }
        }
    }

    // Merge the 4 M-quarters (lanes differing in bits 3,4). Tie -> smaller m.
#pragma unroll
    for (int r = 8; r <= 16; r <<= 1) {
#pragma unroll
        for (int i = 0; i < 4; i++) {
            float ob = __shfl_xor_sync(0xffffffffu, best[i], r);
            int   oi = __shfl_xor_sync(0xffffffffu, bidx[i], r);
            if (ob < best[i] || (ob == best[i] && oi < bidx[i])) {
                best[i] = ob;
                bidx[i] = oi;
            }
        }
    }

    // Lanes with q==0 hold final results; write nearest + min_dist.
    float mloc = 0.0f;
    if (q == 0) {
#pragma unroll
        for (int i = 0; i < 4; i++) {
            int mi = bidx[i];
            float d2 = fmaf(2.0f, best[i], xs[i]);
            float md = sqrtf(fmaxf(d2, 0.0f));
            g_near[b * NN + n0 + i] =
                make_float4(sm[mi], sm[MM + mi], sm[2 * MM + mi], md);
            mloc = fmaxf(mloc, md);
        }
    }

    // Warp max (lanes q!=0 contribute 0), one atomic per warp.
#pragma unroll
    for (int o = 16; o > 0; o >>= 1)
        mloc = fmaxf(mloc, __shfl_xor_sync(0xffffffffu, mloc, o));
    if (lane == 0)
        atomicMax(&g_maxbits[iter * BB + b], __float_as_int(mloc));
}

// ---------------------------------------------------------------------------
// Phase B: blend refined toward nearest with distance-normalized alpha.
// ---------------------------------------------------------------------------
__global__ void ipgr_update_kernel(float* __restrict__ refined, int iter) {
    const int gi = blockIdx.x * blockDim.x + threadIdx.x;  // b*NN + n
    const int b  = gi >> 13;  // NN = 8192

    float4 nd = g_near[gi];
    float  mx = __int_as_float(g_maxbits[iter * BB + b]);
    float  dn = nd.w / (mx + 1e-6f);
    float  alpha = BASE_ALPHA * (2.0f - dn);

    float r0 = refined[gi * 3 + 0];
    float r1 = refined[gi * 3 + 1];
    float r2 = refined[gi * 3 + 2];
    refined[gi * 3 + 0] = fmaf(alpha, nd.x - r0, r0);
    refined[gi * 3 + 1] = fmaf(alpha, nd.y - r1, r1);
    refined[gi * 3 + 2] = fmaf(alpha, nd.z - r2, r2);
}

// ---------------------------------------------------------------------------
extern "C" void kernel_launch(void* const* d_in, const int* in_sizes, int n_in,
                              void* d_out, int out_size) {
    const float* pred    = (const float*)d_in[0];  // [8, 8192, 3] f32
    const float* partial = (const float*)d_in[1];  // [8, 2048, 3] f32
    float* out = (float*)d_out;                     // [8, 8192, 3] f32

    (void)in_sizes; (void)n_in; (void)out_size;

    ipgr_init_kernel<<<192, 256>>>((const float4*)pred, (float4*)out);

    dim3 gridA(NN / 128, BB);  // (64, 8) = 512 blocks
    for (int it = 0; it < NUM_ITER; it++) {
        ipgr_nn_kernel<<<gridA, 128>>>(out, partial, it);
        ipgr_update_kernel<<<(BB * NN) / 256, 256>>>(out, it);
    }
}